// round 1
// baseline (speedup 1.0000x reference)
#include <cuda_runtime.h>

typedef unsigned long long u64;

#define WIDTH    1024
#define HALF     512
#define BATCH    8192
#define DEPTH    20
#define TB       16          // batch columns per block
#define NTHREADS 128         // 32 row-threads x 4 batch4-threads
#define NBLOCKS  (BATCH / TB)

// Precomputed (cos, sin) per (layer, pair). 20*512*8 = 80 KB, stays L2-hot.
__device__ float2 g_cs[DEPTH * HALF];

__global__ void sincos_kernel(const float* __restrict__ ang) {
    int i = blockIdx.x * blockDim.x + threadIdx.x;
    if (i < DEPTH * HALF) {
        float s, c;
        sincosf(ang[i], &s, &c);
        g_cs[i] = make_float2(c, s);
    }
}

// ---- packed f32x2 helpers (sm_100+) ----
__device__ __forceinline__ u64 pk2(float lo, float hi) {
    u64 r; asm("mov.b64 %0, {%1, %2};" : "=l"(r) : "f"(lo), "f"(hi)); return r;
}
__device__ __forceinline__ u64 mul2(u64 a, u64 b) {
    u64 d; asm("mul.rn.f32x2 %0, %1, %2;" : "=l"(d) : "l"(a), "l"(b)); return d;
}
__device__ __forceinline__ u64 fma2(u64 a, u64 b, u64 c) {
    u64 d; asm("fma.rn.f32x2 %0, %1, %2, %3;" : "=l"(d) : "l"(a), "l"(b), "l"(c)); return d;
}

// Givens rotation on 2 packed batches: y0 = c*x0 + s*x1 ; y1 = -s*x0 + c*x1
__device__ __forceinline__ void rot1(u64& x0, u64& x1, u64 cc, u64 ss, u64 ns) {
    u64 t0 = mul2(ss, x1);
    u64 t1 = mul2(cc, x1);
    u64 y0 = fma2(cc, x0, t0);
    x1     = fma2(ns, x0, t1);
    x0     = y0;
}

// Swizzled smem index (units of 16B). XOR keeps every quarter-warp access
// (both row-groupings used below) on 8 distinct 16B bank-groups.
__device__ __forceinline__ int sidx(int row, int b4) {
    return ((row << 2) | b4) ^ (((row >> 5) & 1) << 2);
}

extern "C" __global__ void __launch_bounds__(NTHREADS, 2)
butterfly_kernel(const float* __restrict__ X, float* __restrict__ Y)
{
    extern __shared__ ulonglong2 tile[];   // WIDTH * 4 = 4096 entries = 64 KB

    const int b4 = threadIdx.x & 3;        // which float4 of the 16-batch tile
    const int rt = threadIdx.x >> 2;       // row-thread id, 0..31
    const long long bb = (long long)blockIdx.x * TB + b4 * 4;

    // Each thread holds 32 rows x 4 batches as 2 packed f32x2 per row.
    u64 Xa[32], Xb[32];

    // Load in P1 layout: register j holds row rt*32 + j   (16 sectors/warp, fully coalesced)
#pragma unroll
    for (int j = 0; j < 32; ++j) {
        const ulonglong2 v =
            *reinterpret_cast<const ulonglong2*>(X + (long long)(rt * 32 + j) * BATCH + bb);
        Xa[j] = v.x; Xb[j] = v.y;
    }

#pragma unroll 1
    for (int pass = 0; pass < 2; ++pass) {
        const float2* csbase = g_cs + pass * 10 * HALF;

        if (pass) {
            // Exchange P2 layout (rows rt + 32j) -> P1 layout (rows rt*32 + j)
            __syncthreads();
#pragma unroll
            for (int j = 0; j < 32; ++j)
                tile[sidx(rt + 32 * j, b4)] = make_ulonglong2(Xa[j], Xb[j]);
            __syncthreads();
#pragma unroll
            for (int j = 0; j < 32; ++j) {
                const ulonglong2 v = tile[sidx(rt * 32 + j, b4)];
                Xa[j] = v.x; Xb[j] = v.y;
            }
        }

        // ---- P1: strides 1,2,4,8,16 entirely in registers ----
#pragma unroll
        for (int l = 0; l < 5; ++l) {
            const int s = 1 << l;
            const float2* cs = csbase + l * HALF;
#pragma unroll
            for (int j = 0; j < 32; ++j) {
                if (j & s) continue;                 // compile-time predicate
                const int r0   = rt * 32 + j;
                const int aidx = ((r0 >> 1) & ~(s - 1)) | (r0 & (s - 1));
                const float2 v = __ldg(cs + aidx);
                const u64 cc = pk2(v.x, v.x);
                const u64 ss = pk2(v.y, v.y);
                const u64 ns = pk2(-v.y, -v.y);
                rot1(Xa[j], Xa[j + s], cc, ss, ns);
                rot1(Xb[j], Xb[j + s], cc, ss, ns);
            }
        }

        // Exchange P1 -> P2 layout
        __syncthreads();
#pragma unroll
        for (int j = 0; j < 32; ++j)
            tile[sidx(rt * 32 + j, b4)] = make_ulonglong2(Xa[j], Xb[j]);
        __syncthreads();
#pragma unroll
        for (int j = 0; j < 32; ++j) {
            const ulonglong2 v = tile[sidx(rt + 32 * j, b4)];
            Xa[j] = v.x; Xb[j] = v.y;
        }

        // ---- P2: strides 32,64,128,256,512 in registers (reg pair step = s/32) ----
#pragma unroll
        for (int l = 0; l < 5; ++l) {
            const int s  = 32 << l;
            const int sg = 1 << l;
            const float2* cs = csbase + (5 + l) * HALF;
#pragma unroll
            for (int j = 0; j < 32; ++j) {
                if (j & sg) continue;
                const int r0   = rt + 32 * j;
                const int aidx = ((r0 >> 1) & ~(s - 1)) | (r0 & (s - 1));
                const float2 v = __ldg(cs + aidx);
                const u64 cc = pk2(v.x, v.x);
                const u64 ss = pk2(v.y, v.y);
                const u64 ns = pk2(-v.y, -v.y);
                rot1(Xa[j], Xa[j + sg], cc, ss, ns);
                rot1(Xb[j], Xb[j + sg], cc, ss, ns);
            }
        }
    }

    // Store from P2 layout (rows rt + 32j), coalesced
#pragma unroll
    for (int j = 0; j < 32; ++j) {
        *reinterpret_cast<ulonglong2*>(Y + (long long)(rt + 32 * j) * BATCH + bb) =
            make_ulonglong2(Xa[j], Xb[j]);
    }
}

extern "C" void kernel_launch(void* const* d_in, const int* in_sizes, int n_in,
                              void* d_out, int out_size)
{
    const float* X = (const float*)d_in[0];
    const float* A = (const float*)d_in[1];
    if (n_in >= 2 && in_sizes[0] < in_sizes[1]) {   // defensive: X is the big one
        const float* t = X; X = A; A = t;
    }
    float* Y = (float*)d_out;

    cudaFuncSetAttribute(butterfly_kernel,
                         cudaFuncAttributeMaxDynamicSharedMemorySize, 65536);

    sincos_kernel<<<(DEPTH * HALF + 255) / 256, 256>>>(A);
    butterfly_kernel<<<NBLOCKS, NTHREADS, 65536>>>(X, Y);
}